// round 8
// baseline (speedup 1.0000x reference)
#include <cuda_runtime.h>
#include <math.h>

#define COL 14
#define NJ 23
#define PAIR_ELEMS (COL * COL)   // 196
#define WARPS_PER_BLOCK 8
#define BLOCK_THREADS (WARPS_PER_BLOCK * 32)
#define CHUNK 10                 // 94208/(8*10) -> 1178 blocks ~ one wave

__device__ float        g_sum   = 0.0f;
__device__ unsigned int g_count = 0u;

// gaussian weights exp(-k^2/2)/sum, k=-4..4 (normalized in double, cast to f32)
__device__ __constant__ float c_w[9] = {
    0.000133832f, 0.00443186f, 0.05399111f, 0.24197140f, 0.39894345f,
    0.24197140f, 0.05399111f, 0.00443186f, 0.000133832f
};

// tree node: right wins only on strictly greater (left operand always carries
// the smaller index -> ties keep first occurrence, matching jnp.argmax)
__device__ __forceinline__ void amax_node(float& v, int& i, float vr, int ir) {
    if (vr > v) { v = vr; i = ir; }
}

__global__ __launch_bounds__(BLOCK_THREADS, 8)
void mse3d_kernel(const float* __restrict__ o,
                  const float* __restrict__ h,
                  const float* __restrict__ t,
                  const int*   __restrict__ v,
                  float* __restrict__ out,
                  int n_pairs, int nblocks) {
    // sMt[i*COL + r] = M[r][i]  (column i of M contiguous)
    __shared__ float sMt[PAIR_ELEMS];
    __shared__ float sColMin[COL], sColMax[COL];
    __shared__ float sColS1[COL], sColS2[COL];   // per-column sum, sum of squares
    __shared__ float wsum[WARPS_PER_BLOCK];

    const int tid = threadIdx.x;

    // ---- per-block gaussian matrix build ----
    if (tid < PAIR_ELEMS) {
        const int outr = tid / COL;
        const int i    = tid % COL;
        float m = 0.0f;
        #pragma unroll
        for (int k = -4; k <= 4; k++) {
            int ii = (outr + k + 2 * COL) % (2 * COL);
            if (ii >= COL) ii = 2 * COL - 1 - ii;
            if (ii == i) m += c_w[k + 4];
        }
        sMt[i * COL + outr] = m;
    }
    __syncthreads();
    if (tid < COL) {
        float mn = INFINITY, mx = -INFINITY, s1 = 0.0f, s2 = 0.0f;
        #pragma unroll
        for (int r = 0; r < COL; r++) {
            float val = sMt[tid * COL + r];   // M[r][tid]
            mn = fminf(mn, val);
            mx = fmaxf(mx, val);
            s1 += val;
            s2 = fmaf(val, val, s2);
        }
        sColMin[tid] = mn;
        sColMax[tid] = mx;
        sColS1[tid]  = s1;
        sColS2[tid]  = s2;
    }
    __syncthreads();

    const int lane  = tid & 31;
    const int warp  = tid >> 5;
    const int gwarp = blockIdx.x * WARPS_PER_BLOCK + warp;
    const int pair0 = gwarp * CHUNK;
    const int cnt   = min(CHUNK, n_pairs - pair0);

    float acc  = 0.0f;   // d1
    float acc2 = 0.0f;   // d2 (o gathers) + per-pair constant terms

    if (cnt > 0) {
        const int ia   = lane;            // float4 idx a (< 49 always)
        const int ib   = 32 + lane;       // float4 idx b
        const bool hasb = (ib < 49);      // lanes 0..16

        // per-lane element coordinates, loop-invariant
        const int ea = 4 * ia;
        const int ra0 = ea / COL, ca0 = ea - ra0 * COL;
        const int eb = 4 * ib;
        const int rb0 = eb / COL, cb0 = eb - rb0 * COL;

        // incremental streams (one division per chunk total)
        const float4* hp = (const float4*)(h + (size_t)pair0 * PAIR_ELEMS);
        const float*  tp = t + (size_t)pair0 * 3;
        const int*    vp = v + (size_t)pair0 * 2;
        int bb = pair0 / NJ;
        int jj = pair0 - bb * NJ;
        int rowbase = (bb * (3 * NJ) + jj) * PAIR_ELEMS;   // (b*69+j)*196, int32 ok
        const int laneoff = lane * (NJ * PAIR_ELEMS);      // lane*23*196

        for (int k = 0; k < cnt; k++) {
            // ---- h tile: 49 float4, lanes 0..16 take a second one ----
            float4 va = hp[ia];
            float4 vb = hasb ? hp[ib] : make_float4(0.f, 0.f, 0.f, 0.f);

            // t stride is 12 bytes -> only 4B-aligned; scalar loads only
            const float t0 = tp[0];
            const float t1 = tp[1];
            const float t2 = tp[2];
            const int   vv = vp[0];

            // ---- tree argmax over the 8 local elements ----
            float m0 = va.x; int i0 = ea;
            amax_node(m0, i0, va.y, ea + 1);
            float m1 = va.z; int i1 = ea + 2;
            amax_node(m1, i1, va.w, ea + 3);
            float m2 = vb.x; int i2 = eb;
            amax_node(m2, i2, vb.y, eb + 1);
            float m3 = vb.z; int i3 = eb + 2;
            amax_node(m3, i3, vb.w, eb + 3);
            amax_node(m0, i0, m1, i1);
            amax_node(m2, i2, m3, i3);
            amax_node(m0, i0, m2, i2);
            // h >= 0: float bits order-isomorphic. redux-max on bits, then
            // redux-min on index among maximal lanes (first occurrence).
            const unsigned int bbits = __float_as_uint(m0);
            const unsigned int mbits = __reduce_max_sync(0xffffffffu, bbits);
            const int amax = (int)__reduce_min_sync(
                0xffffffffu, (bbits == mbits) ? (unsigned)i0 : 0xffffffffu);
            const int ay = amax / COL;
            const int ax = amax - ay * COL;

            // ---- d2: 3 gathered o values, one per lane 0..2 ----
            if (lane < 3) {
                const float ov = __ldg(o + (rowbase + laneoff + amax));
                const float scale = 1.0f / (float)COL;
                const float refv = (lane == 0) ? t0 : ((lane == 1) ? t1 : t2);
                const float addv = (lane == 0) ? (float)ax * scale
                                 : ((lane == 1) ? (float)ay * scale : 0.0f);
                const float d = ov + addv - refv;
                acc2 = fmaf(d, d, acc2);
            }

            // ---- always: sum h^2 (mask-independent part of d1) ----
            acc = fmaf(va.x, va.x, acc);
            acc = fmaf(va.y, va.y, acc);
            acc = fmaf(va.z, va.z, acc);
            acc = fmaf(va.w, va.w, acc);
            acc = fmaf(vb.x, vb.x, acc);   // vb is zero for lanes without b
            acc = fmaf(vb.y, vb.y, acc);
            acc = fmaf(vb.z, vb.z, acc);
            acc = fmaf(vb.w, vb.w, acc);

            // ---- mask / normalization params ----
            const int xi = (int)truncf(t0 * (float)COL);
            const int yi = (int)truncf(t1 * (float)COL);
            const bool in_range = (xi >= 0) && (xi <= COL - 1) &&
                                  (yi >= 0) && (yi <= COL - 1);
            const bool mask = (vv == 1) && in_range;

            if (mask) {
                // d1_pair = sum h^2 - 2*sum(h*tt) + sum(tt^2)
                // tt = inv*(gy*gx) + nb, nb = -mn*inv
                // sum(h*tt) = inv*sum(h*gy*gx) + nb*sum(h)   (per-lane partials)
                // sum(tt^2) = inv^2*(S2y*S2x) + 2*inv*nb*(S1y*S1x) + 196*nb^2
                const int xc = min(max(xi, 0), COL - 1);
                const int yc = min(max(yi, 0), COL - 1);
                const float mn  = sColMin[yc] * sColMin[xc];
                const float mx  = sColMax[yc] * sColMax[xc];
                const float inv = 1.0f / (mx - mn);
                const float nb  = -mn * inv;
                const float* gy = &sMt[yc * COL];        // gy[r] = M[r][yc]
                const float* gx = &sMt[xc * COL];        // gx[c] = M[c][xc]

                float hw = 0.0f;   // sum h * gy * gx (lane partial)
                float sh = 0.0f;   // sum h           (lane partial)
                {
                    int r = ra0, c = ca0;
                    float hv[4] = {va.x, va.y, va.z, va.w};
                    #pragma unroll
                    for (int q = 0; q < 4; q++) {
                        hw = fmaf(hv[q], gy[r] * gx[c], hw);
                        sh += hv[q];
                        if (++c == COL) { c = 0; ++r; }
                    }
                }
                if (hasb) {
                    int r = rb0, c = cb0;
                    float hv[4] = {vb.x, vb.y, vb.z, vb.w};
                    #pragma unroll
                    for (int q = 0; q < 4; q++) {
                        hw = fmaf(hv[q], gy[r] * gx[c], hw);
                        sh += hv[q];
                        if (++c == COL) { c = 0; ++r; }
                    }
                }
                // fold cross term per lane: -2*(inv*hw + nb*sh)
                acc = fmaf(-2.0f * inv, hw, acc);
                acc = fmaf(-2.0f * nb,  sh, acc);
                // constant term sum(tt^2), warp-uniform: add on lane 0 only
                if (lane == 0) {
                    const float S1 = sColS1[yc] * sColS1[xc];
                    const float S2 = sColS2[yc] * sColS2[xc];
                    float ct = inv * inv * S2;
                    ct = fmaf(2.0f * inv * nb, S1, ct);
                    ct = fmaf((float)PAIR_ELEMS * nb, nb, ct);
                    acc2 += ct;
                }
            }

            // advance streams
            hp += 49;
            tp += 3;
            vp += 2;
            rowbase += PAIR_ELEMS;
            if (++jj == NJ) { jj = 0; rowbase += (3 * NJ - 1) * PAIR_ELEMS; }
        }
    }

    acc += acc2;

    // ---- block reduction ----
    #pragma unroll
    for (int off = 16; off > 0; off >>= 1)
        acc += __shfl_down_sync(0xffffffffu, acc, off);
    if (lane == 0) wsum[warp] = acc;
    __syncthreads();

    if (warp == 0) {
        float s = (lane < WARPS_PER_BLOCK) ? wsum[lane] : 0.0f;
        #pragma unroll
        for (int off = WARPS_PER_BLOCK / 2; off > 0; off >>= 1)
            s += __shfl_down_sync(0xffffffffu, s, off);
        if (lane == 0) {
            atomicAdd(&g_sum, s * (1.0f / (float)NJ));
            __threadfence();
            unsigned int done = atomicAdd(&g_count, 1u);
            if (done == (unsigned)nblocks - 1) {
                float total = atomicExch(&g_sum, 0.0f);
                out[0] = total;
                g_count = 0u;
                __threadfence();
            }
        }
    }
}

extern "C" void kernel_launch(void* const* d_in, const int* in_sizes, int n_in,
                              void* d_out, int out_size) {
    const float* o = (const float*)d_in[0];
    const float* h = (const float*)d_in[1];
    const float* t = (const float*)d_in[2];
    const int*   v = (const int*)d_in[3];
    float* out = (float*)d_out;

    const int n_pairs = in_sizes[1] / PAIR_ELEMS;   // B * NJ from h
    const int pairs_per_block = WARPS_PER_BLOCK * CHUNK;
    const int blocks = (n_pairs + pairs_per_block - 1) / pairs_per_block;

    mse3d_kernel<<<blocks, BLOCK_THREADS>>>(o, h, t, v, out, n_pairs, blocks);
}

// round 9
// speedup vs baseline: 1.0738x; 1.0738x over previous
#include <cuda_runtime.h>
#include <math.h>

#define COL 14
#define NJ 23
#define PAIR_ELEMS (COL * COL)   // 196
#define WARPS_PER_BLOCK 8
#define BLOCK_THREADS (WARPS_PER_BLOCK * 32)
#define CHUNK 10                 // 94208/(8*10) -> 1178 blocks ~ one wave

__device__ float        g_sum   = 0.0f;
__device__ unsigned int g_count = 0u;

// gaussian weights exp(-k^2/2)/sum, k=-4..4 (normalized in double, cast to f32)
__device__ __constant__ float c_w[9] = {
    0.000133832f, 0.00443186f, 0.05399111f, 0.24197140f, 0.39894345f,
    0.24197140f, 0.05399111f, 0.00443186f, 0.000133832f
};

// tree node: right wins only on strictly greater (left operand always carries
// the smaller index -> ties keep first occurrence, matching jnp.argmax)
__device__ __forceinline__ void amax_node(float& v, int& i, float vr, int ir) {
    if (vr > v) { v = vr; i = ir; }
}

__global__ __launch_bounds__(BLOCK_THREADS, 8)
void mse3d_kernel(const float* __restrict__ o,
                  const float* __restrict__ h,
                  const float* __restrict__ t,
                  const int*   __restrict__ v,
                  float* __restrict__ out,
                  int n_pairs, int nblocks) {
    // sMt[i*COL + r] = M[r][i]  (column i of M contiguous)
    __shared__ float sMt[PAIR_ELEMS];
    __shared__ float sColMin[COL], sColMax[COL];
    __shared__ float sColS1[COL], sColS2[COL];   // per-column sum, sum of squares
    __shared__ float wsum[WARPS_PER_BLOCK];

    const int tid = threadIdx.x;

    // ---- per-block gaussian matrix build ----
    if (tid < PAIR_ELEMS) {
        const int outr = tid / COL;
        const int i    = tid % COL;
        float m = 0.0f;
        #pragma unroll
        for (int k = -4; k <= 4; k++) {
            int ii = (outr + k + 2 * COL) % (2 * COL);
            if (ii >= COL) ii = 2 * COL - 1 - ii;
            if (ii == i) m += c_w[k + 4];
        }
        sMt[i * COL + outr] = m;
    }
    __syncthreads();
    if (tid < COL) {
        float mn = INFINITY, mx = -INFINITY, s1 = 0.0f, s2 = 0.0f;
        #pragma unroll
        for (int r = 0; r < COL; r++) {
            float val = sMt[tid * COL + r];   // M[r][tid]
            mn = fminf(mn, val);
            mx = fmaxf(mx, val);
            s1 += val;
            s2 = fmaf(val, val, s2);
        }
        sColMin[tid] = mn;
        sColMax[tid] = mx;
        sColS1[tid]  = s1;
        sColS2[tid]  = s2;
    }
    __syncthreads();

    const int lane  = tid & 31;
    const int warp  = tid >> 5;
    const int gwarp = blockIdx.x * WARPS_PER_BLOCK + warp;
    const int pair0 = gwarp * CHUNK;
    const int cnt   = min(CHUNK, n_pairs - pair0);

    float acc  = 0.0f;   // d1
    float acc2 = 0.0f;   // d2 + per-pair constant terms

    if (cnt > 0) {
        const int ia   = lane;            // float4 idx a (< 49 always)
        const int ib   = 32 + lane;       // float4 idx b
        const bool hasb = (ib < 49);      // lanes 0..16

        // per-lane element coordinates, loop-invariant
        const int ea = 4 * ia;
        const int ra0 = ea / COL, ca0 = ea - ra0 * COL;
        const int eb = 4 * ib;
        const int rb0 = eb / COL, cb0 = eb - rb0 * COL;

        const float4* hp = (const float4*)(h + (size_t)pair0 * PAIR_ELEMS);
        const float*  tp = t + (size_t)pair0 * 3;
        const int*    vp = v + (size_t)pair0 * 2;

        int myAmax = 0;   // lane k banks pair k's argmax

        // ================= Phase 1: h-only (d1 + argmax) =================
        for (int k = 0; k < cnt; k++) {
            float4 va = hp[ia];
            float4 vb = hasb ? hp[ib] : make_float4(0.f, 0.f, 0.f, 0.f);

            const float t0 = tp[0];
            const float t1 = tp[1];
            const int   vv = vp[0];

            // ---- tree argmax over the 8 local elements ----
            float m0 = va.x; int i0 = ea;
            amax_node(m0, i0, va.y, ea + 1);
            float m1 = va.z; int i1 = ea + 2;
            amax_node(m1, i1, va.w, ea + 3);
            float m2 = vb.x; int i2 = eb;
            amax_node(m2, i2, vb.y, eb + 1);
            float m3 = vb.z; int i3 = eb + 2;
            amax_node(m3, i3, vb.w, eb + 3);
            amax_node(m0, i0, m1, i1);
            amax_node(m2, i2, m3, i3);
            amax_node(m0, i0, m2, i2);
            // h >= 0: float bits order-isomorphic. redux-max on bits, then
            // redux-min on index among maximal lanes (first occurrence).
            const unsigned int bbits = __float_as_uint(m0);
            const unsigned int mbits = __reduce_max_sync(0xffffffffu, bbits);
            const int amax = (int)__reduce_min_sync(
                0xffffffffu, (bbits == mbits) ? (unsigned)i0 : 0xffffffffu);
            if (lane == k) myAmax = amax;   // bank for phase 2

            // ---- always: sum h^2 (mask-independent part of d1) ----
            acc = fmaf(va.x, va.x, acc);
            acc = fmaf(va.y, va.y, acc);
            acc = fmaf(va.z, va.z, acc);
            acc = fmaf(va.w, va.w, acc);
            acc = fmaf(vb.x, vb.x, acc);   // vb is zero for lanes without b
            acc = fmaf(vb.y, vb.y, acc);
            acc = fmaf(vb.z, vb.z, acc);
            acc = fmaf(vb.w, vb.w, acc);

            // ---- mask / normalization params ----
            const int xi = (int)truncf(t0 * (float)COL);
            const int yi = (int)truncf(t1 * (float)COL);
            const bool in_range = (xi >= 0) && (xi <= COL - 1) &&
                                  (yi >= 0) && (yi <= COL - 1);
            const bool mask = (vv == 1) && in_range;

            if (mask) {
                // d1_pair = sum h^2 - 2*sum(h*tt) + sum(tt^2)
                // tt = inv*(gy*gx) + nb, nb = -mn*inv
                const int xc = min(max(xi, 0), COL - 1);
                const int yc = min(max(yi, 0), COL - 1);
                const float mn  = sColMin[yc] * sColMin[xc];
                const float mx  = sColMax[yc] * sColMax[xc];
                const float inv = 1.0f / (mx - mn);
                const float nb  = -mn * inv;
                const float* gy = &sMt[yc * COL];        // gy[r] = M[r][yc]
                const float* gx = &sMt[xc * COL];        // gx[c] = M[c][xc]

                float hw = 0.0f;   // sum h * gy * gx (lane partial)
                float sh = 0.0f;   // sum h           (lane partial)
                {
                    int r = ra0, c = ca0;
                    float hv[4] = {va.x, va.y, va.z, va.w};
                    #pragma unroll
                    for (int q = 0; q < 4; q++) {
                        hw = fmaf(hv[q], gy[r] * gx[c], hw);
                        sh += hv[q];
                        if (++c == COL) { c = 0; ++r; }
                    }
                }
                if (hasb) {
                    int r = rb0, c = cb0;
                    float hv[4] = {vb.x, vb.y, vb.z, vb.w};
                    #pragma unroll
                    for (int q = 0; q < 4; q++) {
                        hw = fmaf(hv[q], gy[r] * gx[c], hw);
                        sh += hv[q];
                        if (++c == COL) { c = 0; ++r; }
                    }
                }
                acc = fmaf(-2.0f * inv, hw, acc);
                acc = fmaf(-2.0f * nb,  sh, acc);
                // constant term sum(tt^2), warp-uniform: lane 0 only
                if (lane == 0) {
                    const float S1 = sColS1[yc] * sColS1[xc];
                    const float S2 = sColS2[yc] * sColS2[xc];
                    float ct = inv * inv * S2;
                    ct = fmaf(2.0f * inv * nb, S1, ct);
                    ct = fmaf((float)PAIR_ELEMS * nb, nb, ct);
                    acc2 += ct;
                }
            }

            hp += 49;
            tp += 3;
            vp += 2;
        }

        // ====== Phase 2: all o-gathers at once (30 concurrent loads) ======
        {
            const int kq   = min(lane / 3, cnt - 1);     // clamped for shfl
            const int am   = __shfl_sync(0xffffffffu, myAmax, kq);
            if (lane < 3 * cnt) {
                const int k    = lane / 3;
                const int comp = lane - 3 * k;
                const int pair = pair0 + k;
                const int b    = pair / NJ;
                const int j    = pair - b * NJ;
                const int ayk  = am / COL;
                const int axk  = am - ayk * COL;
                const int row  = b * (3 * NJ) + j + comp * NJ;
                const float ov = __ldg(o + ((size_t)row * PAIR_ELEMS + am));
                // refv = t[pair*3 + comp] = t[pair0*3 + lane]  (coalesced)
                const float refv = t[(size_t)pair0 * 3 + lane];
                const float scale = 1.0f / (float)COL;
                const float addv = (comp == 0) ? (float)axk * scale
                                 : ((comp == 1) ? (float)ayk * scale : 0.0f);
                const float d = ov + addv - refv;
                acc2 = fmaf(d, d, acc2);
            }
        }
    }

    acc += acc2;

    // ---- block reduction ----
    #pragma unroll
    for (int off = 16; off > 0; off >>= 1)
        acc += __shfl_down_sync(0xffffffffu, acc, off);
    if (lane == 0) wsum[warp] = acc;
    __syncthreads();

    if (warp == 0) {
        float s = (lane < WARPS_PER_BLOCK) ? wsum[lane] : 0.0f;
        #pragma unroll
        for (int off = WARPS_PER_BLOCK / 2; off > 0; off >>= 1)
            s += __shfl_down_sync(0xffffffffu, s, off);
        if (lane == 0) {
            atomicAdd(&g_sum, s * (1.0f / (float)NJ));
            __threadfence();
            unsigned int done = atomicAdd(&g_count, 1u);
            if (done == (unsigned)nblocks - 1) {
                float total = atomicExch(&g_sum, 0.0f);
                out[0] = total;
                g_count = 0u;
                __threadfence();
            }
        }
    }
}

extern "C" void kernel_launch(void* const* d_in, const int* in_sizes, int n_in,
                              void* d_out, int out_size) {
    const float* o = (const float*)d_in[0];
    const float* h = (const float*)d_in[1];
    const float* t = (const float*)d_in[2];
    const int*   v = (const int*)d_in[3];
    float* out = (float*)d_out;

    const int n_pairs = in_sizes[1] / PAIR_ELEMS;   // B * NJ from h
    const int pairs_per_block = WARPS_PER_BLOCK * CHUNK;
    const int blocks = (n_pairs + pairs_per_block - 1) / pairs_per_block;

    mse3d_kernel<<<blocks, BLOCK_THREADS>>>(o, h, t, v, out, n_pairs, blocks);
}